// round 14
// baseline (speedup 1.0000x reference)
#include <cuda_runtime.h>
#include <math.h>

// ChamferLoss bs=4, npts=4096, dim=3 — FUSED: each dist^2 computed ONCE.
// t = xsq - 2 x.y (3 fma2, seed xsq): row-min (per y) exact on t (ysq const/row).
// u = t + ysq (1 add2): col-min (per x) on full dist^2.
// Row cross-lane min: 5-step shfl.bfly tree per (y, warp) (~25% issue overhead,
// latency-tolerant: result only feeds a store).
// Each lane owns 8 x in registers (col-mins in regs). Grid: 2 xh x 16 yb x 4 b
// = 128 blocks = one wave. Per-batch finishers via self-resetting counters.

#define NPTS 4096
#define BS   4
#define TPB  256
#define NWARP 8
#define YB   256                  // y rows per block
#define NYB  (NPTS / YB)          // 16
#define XH   2048                 // x per block (half)
#define XPW  (XH / NWARP)         // 256 x per warp
#define SLOTS 4                   // packed x-pairs per lane (8 x per lane)
#define BPB  (2 * NYB)            // 32 blocks per batch

__device__ float g_colpart[BS * NYB * NPTS];   // [b][yb][x] (1 MB)
__device__ float g_rowpart[BS * NPTS * 2];     // [b][y][xh]
__device__ float g_bsum[BS];
__device__ unsigned int g_bc[BS];              // zero-init, self-resetting
__device__ unsigned int g_fc;                  // zero-init, self-resetting

typedef unsigned long long ull;

__device__ __forceinline__ ull pack2(float a, float b) {
    ull v;
    asm("mov.b64 %0, {%1, %2};" : "=l"(v) : "r"(__float_as_uint(a)), "r"(__float_as_uint(b)));
    return v;
}
__device__ __forceinline__ void unpack2(ull v, float& a, float& b) {
    unsigned lo, hi;
    asm("mov.b64 {%0, %1}, %2;" : "=r"(lo), "=r"(hi) : "l"(v));
    a = __uint_as_float(lo); b = __uint_as_float(hi);
}
__device__ __forceinline__ ull fma2(ull a, ull b, ull c) {
    ull d;
    asm("fma.rn.f32x2 %0, %1, %2, %3;" : "=l"(d) : "l"(a), "l"(b), "l"(c));
    return d;
}
__device__ __forceinline__ ull add2(ull a, ull b) {
    ull d;
    asm("add.rn.f32x2 %0, %1, %2;" : "=l"(d) : "l"(a), "l"(b));
    return d;
}
__device__ __forceinline__ float warp_min(float v) {
    #pragma unroll
    for (int off = 16; off; off >>= 1)
        v = fminf(v, __shfl_xor_sync(0xFFFFFFFFu, v, off));
    return v;
}

__global__ __launch_bounds__(TPB, 1) void chamfer_fused(
    const float* __restrict__ x, const float* __restrict__ y, float* __restrict__ out)
{
    __shared__ __align__(16) float sy[YB * 8 + 16];    // 8KB + pad (prefetch overrun)
    __shared__ float srow[NWARP * YB];                 // 8KB: [w][y]
    __shared__ float red[NWARP];
    __shared__ int   s_last;

    const int tid  = threadIdx.x;
    const int lane = tid & 31;
    const int w    = tid >> 5;
    const int xh   = blockIdx.x;          // 0..1
    const int yb   = blockIdx.y;          // 0..NYB-1
    const int b    = blockIdx.z;          // 0..BS-1

    // Stage y-tile: per y 32B {yx,yx, yy,yy, yz,yz, ysq,ysq}.
    if (tid < YB) {
        const float* yp = y + ((size_t)b * NPTS + (size_t)yb * YB + tid) * 3;
        float a = yp[0], c = yp[1], d = yp[2];
        float qs = fmaf(a, a, fmaf(c, c, d * d));
        float4* o = (float4*)(sy + tid * 8);
        o[0] = make_float4(a, a, c, c);
        o[1] = make_float4(d, d, qs, qs);
    }
    if (tid >= TPB - 16) sy[YB * 8 + (tid - (TPB - 16))] = 0.0f;   // pad

    // Lane's 8 x-points -> packed registers (xsq as chain seed).
    ull Xp[SLOTS], Yq[SLOTS], Zp[SLOTS], Hp[SLOTS];
    {
        const float* xb = x + ((size_t)b * NPTS + (size_t)xh * XH + (size_t)w * XPW) * 3;
        #pragma unroll
        for (int j = 0; j < SLOTS; ++j) {
            int i0 = (2 * j) * 32 + lane;
            int i1 = i0 + 32;
            float x0 = xb[3 * i0 + 0], y0 = xb[3 * i0 + 1], z0 = xb[3 * i0 + 2];
            float x1 = xb[3 * i1 + 0], y1 = xb[3 * i1 + 1], z1 = xb[3 * i1 + 2];
            Xp[j] = pack2(-2.0f * x0, -2.0f * x1);
            Yq[j] = pack2(-2.0f * y0, -2.0f * y1);
            Zp[j] = pack2(-2.0f * z0, -2.0f * z1);
            Hp[j] = pack2(fmaf(x0, x0, fmaf(y0, y0, z0 * z0)),
                          fmaf(x1, x1, fmaf(y1, y1, z1 * z1)));
        }
    }

    float colacc[2 * SLOTS];
    #pragma unroll
    for (int k = 0; k < 2 * SLOTS; ++k) colacc[k] = 3.402823466e+38f;

    __syncthreads();

    unsigned sya = (unsigned)__cvta_generic_to_shared(sy);

    #define YLOAD(A_, B_, off)                                                     \
        asm("ld.shared.v2.u64 {%0,%1}, [%2+" #off "];" : "=l"(A_), "=l"(B_) : "r"(sya))

    ull Ya0, Yb0, Yc0, Ys0, Ya1, Yb1, Yc1, Ys1;
    YLOAD(Ya0, Yb0, 0); YLOAD(Yc0, Ys0, 16);

    #define YBODY(YA, YBv, YC, YS, yy)                                             \
        {                                                                          \
            float rm = 3.402823466e+38f;                                           \
            _Pragma("unroll")                                                      \
            for (int j = 0; j < SLOTS; ++j) {                                      \
                ull t = fma2(Xp[j], (YA), Hp[j]);                                  \
                t = fma2(Yq[j], (YBv), t);                                         \
                t = fma2(Zp[j], (YC), t);                                          \
                ull u = add2(t, (YS));                                             \
                float c0, c1, r0, r1;                                              \
                unpack2(u, c0, c1);                                                \
                colacc[2 * j]     = fminf(colacc[2 * j], c0);                      \
                colacc[2 * j + 1] = fminf(colacc[2 * j + 1], c1);                  \
                unpack2(t, r0, r1);                                                \
                rm = fminf(rm, fminf(r0, r1));                                     \
            }                                                                      \
            rm = warp_min(rm);                                                     \
            if (lane == 0) srow[w * YB + (yy)] = rm;                               \
        }

    #pragma unroll 1
    for (int yy = 0; yy < YB; yy += 2) {
        sya += 64;
        YLOAD(Ya1, Yb1, -32); YLOAD(Yc1, Ys1, -16);    // prefetch yy+1
        YBODY(Ya0, Yb0, Yc0, Ys0, yy);
        YLOAD(Ya0, Yb0, 0);   YLOAD(Yc0, Ys0, 16);     // prefetch yy+2 (pad last)
        YBODY(Ya1, Yb1, Yc1, Ys1, yy + 1);
    }
    #undef YBODY
    #undef YLOAD

    __syncthreads();

    // Row combine (min over 8 warps) -> global [b][y][xh]. t-values (no ysq yet).
    if (tid < YB) {
        float m = srow[tid];
        #pragma unroll
        for (int ww = 1; ww < NWARP; ++ww) m = fminf(m, srow[ww * YB + tid]);
        g_rowpart[((size_t)b * NPTS + (yb * YB + tid)) * 2 + xh] = m;
    }

    // Col partials -> global (coalesced).
    {
        float* cp = &g_colpart[((size_t)b * NYB + yb) * NPTS + (size_t)xh * XH + (size_t)w * XPW];
        #pragma unroll
        for (int kk = 0; kk < 2 * SLOTS; ++kk)
            cp[kk * 32 + lane] = colacc[kk];
    }

    // ---- Per-batch finisher (last of 32 blocks for batch b). ----
    __threadfence();
    if (tid == 0)
        s_last = (atomicAdd(&g_bc[b], 1u) == BPB - 1) ? 1 : 0;
    __syncthreads();

    if (s_last) {
        if (tid == 0) g_bc[b] = 0;         // self-reset for graph replay
        float acc = 0.0f;
        // Cols: per x, min over 16 yb partials (full dist^2 already).
        #pragma unroll 2
        for (int xi = tid; xi < NPTS; xi += TPB) {
            float m = 3.402823466e+38f;
            #pragma unroll
            for (int u = 0; u < NYB; ++u)
                m = fminf(m, __ldcg(&g_colpart[((size_t)b * NYB + u) * NPTS + xi]));
            acc += sqrtf(1e-6f + m);
        }
        // Rows: per y, min over 2 xh partials, then + ysq.
        #pragma unroll 2
        for (int yi = tid; yi < NPTS; yi += TPB) {
            const float* rp = &g_rowpart[((size_t)b * NPTS + yi) * 2];
            float m = fminf(__ldcg(rp), __ldcg(rp + 1));
            const float* yp = y + ((size_t)b * NPTS + yi) * 3;
            float a = yp[0], c = yp[1], d = yp[2];
            float ysq = fmaf(a, a, fmaf(c, c, d * d));
            acc += sqrtf(1e-6f + m + ysq);
        }
        #pragma unroll
        for (int off = 16; off; off >>= 1)
            acc += __shfl_down_sync(0xFFFFFFFFu, acc, off);
        if (lane == 0) red[w] = acc;
        __syncthreads();
        if (tid == 0) {
            float t = 0.0f;
            #pragma unroll
            for (int i = 0; i < NWARP; ++i) t += red[i];
            g_bsum[b] = t;
            __threadfence();
            if (atomicAdd(&g_fc, 1u) == BS - 1) {
                volatile float* gs = g_bsum;
                float tot = gs[0] + gs[1] + gs[2] + gs[3];
                out[0] = tot * (1.0f / 16384.0f);   // (S1 + S2) / (BS * NPTS)
                g_fc = 0;                            // self-reset
            }
        }
    }
}

extern "C" void kernel_launch(void* const* d_in, const int* in_sizes, int n_in,
                              void* d_out, int out_size)
{
    const float* x = (const float*)d_in[0];
    const float* y = (const float*)d_in[1];
    float* out = (float*)d_out;

    chamfer_fused<<<dim3(2, NYB, BS), TPB>>>(x, y, out);
}

// round 15
// speedup vs baseline: 1.2201x; 1.2201x over previous
#include <cuda_runtime.h>
#include <math.h>

// ChamferLoss bs=4, npts=4096, dim=3 — FUSED: each dist^2 computed ONCE.
// u = xsq - 2 x.y + ysq (3 fma2 + 1 add2, packed f32x2) serves BOTH reductions:
// col-min (per x) in registers; row-min (per y) via fp-bits-as-u32
// redux.sync.min.u32 (u >= 0 -> exact), one instruction per (y, warp).
// Each lane owns 8 x in registers. Grid: 2 xh x 16 yb x 4 b = 128 blocks = one
// wave. Per-batch finishers via self-resetting counters (deterministic).

#define NPTS 4096
#define BS   4
#define TPB  256
#define NWARP 8
#define YB   256                  // y rows per block
#define NYB  (NPTS / YB)          // 16
#define XH   2048                 // x per block (half)
#define XPW  (XH / NWARP)         // 256 x per warp
#define SLOTS 4                   // packed x-pairs per lane (8 x per lane)
#define BPB  (2 * NYB)            // 32 blocks per batch

__device__ float g_colpart[BS * NYB * NPTS];   // [b][yb][x] (1 MB)
__device__ float g_rowpart[BS * NPTS * 2];     // [b][y][xh]
__device__ float g_bsum[BS];
__device__ unsigned int g_bc[BS];              // zero-init, self-resetting
__device__ unsigned int g_fc;                  // zero-init, self-resetting

typedef unsigned long long ull;

__device__ __forceinline__ ull pack2(float a, float b) {
    ull v;
    asm("mov.b64 %0, {%1, %2};" : "=l"(v) : "r"(__float_as_uint(a)), "r"(__float_as_uint(b)));
    return v;
}
__device__ __forceinline__ void unpack2(ull v, float& a, float& b) {
    unsigned lo, hi;
    asm("mov.b64 {%0, %1}, %2;" : "=r"(lo), "=r"(hi) : "l"(v));
    a = __uint_as_float(lo); b = __uint_as_float(hi);
}
__device__ __forceinline__ ull fma2(ull a, ull b, ull c) {
    ull d;
    asm("fma.rn.f32x2 %0, %1, %2, %3;" : "=l"(d) : "l"(a), "l"(b), "l"(c));
    return d;
}
__device__ __forceinline__ ull add2(ull a, ull b) {
    ull d;
    asm("add.rn.f32x2 %0, %1, %2;" : "=l"(d) : "l"(a), "l"(b));
    return d;
}
// Exact fp-min across the warp for non-negative floats (bit-monotone as u32).
__device__ __forceinline__ float warp_min_nonneg(float v) {
    unsigned r;
    asm("redux.sync.min.u32 %0, %1, 0xffffffff;" : "=r"(r) : "r"(__float_as_uint(v)));
    return __uint_as_float(r);
}

__global__ __launch_bounds__(TPB, 1) void chamfer_fused(
    const float* __restrict__ x, const float* __restrict__ y, float* __restrict__ out)
{
    __shared__ __align__(16) float sy[YB * 8 + 16];    // 8KB + pad (prefetch overrun)
    __shared__ float srow[NWARP * YB];                 // 8KB: [w][y]
    __shared__ float red[NWARP];
    __shared__ int   s_last;

    const int tid  = threadIdx.x;
    const int lane = tid & 31;
    const int w    = tid >> 5;
    const int xh   = blockIdx.x;          // 0..1
    const int yb   = blockIdx.y;          // 0..NYB-1
    const int b    = blockIdx.z;          // 0..BS-1

    // Stage y-tile: per y 32B {yx,yx, yy,yy, yz,yz, ysq,ysq}.
    if (tid < YB) {
        const float* yp = y + ((size_t)b * NPTS + (size_t)yb * YB + tid) * 3;
        float a = yp[0], c = yp[1], d = yp[2];
        float qs = fmaf(a, a, fmaf(c, c, d * d));
        float4* o = (float4*)(sy + tid * 8);
        o[0] = make_float4(a, a, c, c);
        o[1] = make_float4(d, d, qs, qs);
    }
    if (tid >= TPB - 16) sy[YB * 8 + (tid - (TPB - 16))] = 0.0f;   // pad

    // Lane's 8 x-points -> packed registers (xsq as chain seed).
    ull Xp[SLOTS], Yq[SLOTS], Zp[SLOTS], Hp[SLOTS];
    {
        const float* xb = x + ((size_t)b * NPTS + (size_t)xh * XH + (size_t)w * XPW) * 3;
        #pragma unroll
        for (int j = 0; j < SLOTS; ++j) {
            int i0 = (2 * j) * 32 + lane;
            int i1 = i0 + 32;
            float x0 = xb[3 * i0 + 0], y0 = xb[3 * i0 + 1], z0 = xb[3 * i0 + 2];
            float x1 = xb[3 * i1 + 0], y1 = xb[3 * i1 + 1], z1 = xb[3 * i1 + 2];
            Xp[j] = pack2(-2.0f * x0, -2.0f * x1);
            Yq[j] = pack2(-2.0f * y0, -2.0f * y1);
            Zp[j] = pack2(-2.0f * z0, -2.0f * z1);
            Hp[j] = pack2(fmaf(x0, x0, fmaf(y0, y0, z0 * z0)),
                          fmaf(x1, x1, fmaf(y1, y1, z1 * z1)));
        }
    }

    float colacc[2 * SLOTS];
    #pragma unroll
    for (int k = 0; k < 2 * SLOTS; ++k) colacc[k] = 3.402823466e+38f;

    __syncthreads();

    unsigned sya = (unsigned)__cvta_generic_to_shared(sy);

    #define YLOAD(A_, B_, off)                                                     \
        asm("ld.shared.v2.u64 {%0,%1}, [%2+" #off "];" : "=l"(A_), "=l"(B_) : "r"(sya))

    ull Ya0, Yb0, Yc0, Ys0, Ya1, Yb1, Yc1, Ys1;
    YLOAD(Ya0, Yb0, 0); YLOAD(Yc0, Ys0, 16);

    #define YBODY(YA, YBv, YC, YS, yy)                                             \
        {                                                                          \
            float rm = 3.402823466e+38f;                                           \
            _Pragma("unroll")                                                      \
            for (int j = 0; j < SLOTS; ++j) {                                      \
                ull t = fma2(Xp[j], (YA), Hp[j]);                                  \
                t = fma2(Yq[j], (YBv), t);                                         \
                t = fma2(Zp[j], (YC), t);                                          \
                ull u = add2(t, (YS));         /* full dist^2, >= 0 */             \
                float c0, c1;                                                      \
                unpack2(u, c0, c1);                                                \
                colacc[2 * j]     = fminf(colacc[2 * j], c0);                      \
                colacc[2 * j + 1] = fminf(colacc[2 * j + 1], c1);                  \
                rm = fminf(rm, fminf(c0, c1));                                     \
            }                                                                      \
            rm = warp_min_nonneg(rm);                                              \
            if (lane == 0) srow[w * YB + (yy)] = rm;                               \
        }

    #pragma unroll 1
    for (int yy = 0; yy < YB; yy += 2) {
        sya += 64;
        YLOAD(Ya1, Yb1, -32); YLOAD(Yc1, Ys1, -16);    // prefetch yy+1
        YBODY(Ya0, Yb0, Yc0, Ys0, yy);
        YLOAD(Ya0, Yb0, 0);   YLOAD(Yc0, Ys0, 16);     // prefetch yy+2 (pad last)
        YBODY(Ya1, Yb1, Yc1, Ys1, yy + 1);
    }
    #undef YBODY
    #undef YLOAD

    __syncthreads();

    // Row combine (min over 8 warps) -> global [b][y][xh] (full dist^2).
    if (tid < YB) {
        float m = srow[tid];
        #pragma unroll
        for (int ww = 1; ww < NWARP; ++ww) m = fminf(m, srow[ww * YB + tid]);
        g_rowpart[((size_t)b * NPTS + (yb * YB + tid)) * 2 + xh] = m;
    }

    // Col partials -> global (coalesced).
    {
        float* cp = &g_colpart[((size_t)b * NYB + yb) * NPTS + (size_t)xh * XH + (size_t)w * XPW];
        #pragma unroll
        for (int kk = 0; kk < 2 * SLOTS; ++kk)
            cp[kk * 32 + lane] = colacc[kk];
    }

    // ---- Per-batch finisher (last of 32 blocks for batch b). ----
    __threadfence();
    if (tid == 0)
        s_last = (atomicAdd(&g_bc[b], 1u) == BPB - 1) ? 1 : 0;
    __syncthreads();

    if (s_last) {
        if (tid == 0) g_bc[b] = 0;         // self-reset for graph replay
        float acc = 0.0f;
        // Cols: per x, min over 16 yb partials.
        #pragma unroll 2
        for (int xi = tid; xi < NPTS; xi += TPB) {
            float m = 3.402823466e+38f;
            #pragma unroll
            for (int u = 0; u < NYB; ++u)
                m = fminf(m, __ldcg(&g_colpart[((size_t)b * NYB + u) * NPTS + xi]));
            acc += sqrtf(1e-6f + m);
        }
        // Rows: per y, min over 2 xh partials.
        #pragma unroll 2
        for (int yi = tid; yi < NPTS; yi += TPB) {
            const float* rp = &g_rowpart[((size_t)b * NPTS + yi) * 2];
            float m = fminf(__ldcg(rp), __ldcg(rp + 1));
            acc += sqrtf(1e-6f + m);
        }
        #pragma unroll
        for (int off = 16; off; off >>= 1)
            acc += __shfl_down_sync(0xFFFFFFFFu, acc, off);
        if (lane == 0) red[w] = acc;
        __syncthreads();
        if (tid == 0) {
            float t = 0.0f;
            #pragma unroll
            for (int i = 0; i < NWARP; ++i) t += red[i];
            g_bsum[b] = t;
            __threadfence();
            if (atomicAdd(&g_fc, 1u) == BS - 1) {
                volatile float* gs = g_bsum;
                float tot = gs[0] + gs[1] + gs[2] + gs[3];
                out[0] = tot * (1.0f / 16384.0f);   // (S1 + S2) / (BS * NPTS)
                g_fc = 0;                            // self-reset
            }
        }
    }
}

extern "C" void kernel_launch(void* const* d_in, const int* in_sizes, int n_in,
                              void* d_out, int out_size)
{
    const float* x = (const float*)d_in[0];
    const float* y = (const float*)d_in[1];
    float* out = (float*)d_out;

    chamfer_fused<<<dim3(2, NYB, BS), TPB>>>(x, y, out);
}

// round 17
// speedup vs baseline: 1.2858x; 1.0539x over previous
#include <cuda_runtime.h>
#include <math.h>

// ChamferLoss bs=4, npts=4096, dim=3 — FUSED: each dist^2 computed ONCE.
// u = xsq - 2 x.y + ysq (3 fma2 + 1 add2, packed f32x2) serves BOTH mins:
// col-min (per x) in registers; row-min (per y) via fp-bits-as-u32
// redux.sync.min.u32 (u >= 0 -> exact), one instruction per (y, warp).
// TPB=512 (4 warps/SMSP) hides redux/LDS latency; each lane owns 4 x.
// Grid: 2 xh x 16 yb x 4 b = 128 blocks = one wave. Per-batch finishers via
// self-resetting counters (deterministic, graph-replayable).

#define NPTS 4096
#define BS   4
#define TPB  512
#define NWARP 16
#define YB   256                  // y rows per block
#define NYB  (NPTS / YB)          // 16
#define XH   2048                 // x per block (half)
#define XPW  (XH / NWARP)         // 128 x per warp
#define SLOTS 2                   // packed x-pairs per lane (4 x per lane)
#define BPB  (2 * NYB)            // 32 blocks per batch

__device__ float g_colpart[BS * NYB * NPTS];   // [b][yb][x] (1 MB)
__device__ float g_rowpart[BS * NPTS * 2];     // [b][y][xh]
__device__ float g_bsum[BS];
__device__ unsigned int g_bc[BS];              // zero-init, self-resetting
__device__ unsigned int g_fc;                  // zero-init, self-resetting

typedef unsigned long long ull;

__device__ __forceinline__ ull pack2(float a, float b) {
    ull v;
    asm("mov.b64 %0, {%1, %2};" : "=l"(v) : "r"(__float_as_uint(a)), "r"(__float_as_uint(b)));
    return v;
}
__device__ __forceinline__ void unpack2(ull v, float& a, float& b) {
    unsigned lo, hi;
    asm("mov.b64 {%0, %1}, %2;" : "=r"(lo), "=r"(hi) : "l"(v));
    a = __uint_as_float(lo); b = __uint_as_float(hi);
}
__device__ __forceinline__ ull fma2(ull a, ull b, ull c) {
    ull d;
    asm("fma.rn.f32x2 %0, %1, %2, %3;" : "=l"(d) : "l"(a), "l"(b), "l"(c));
    return d;
}
__device__ __forceinline__ ull add2(ull a, ull b) {
    ull d;
    asm("add.rn.f32x2 %0, %1, %2;" : "=l"(d) : "l"(a), "l"(b));
    return d;
}
// Exact fp-min across the warp for non-negative floats (bit-monotone as u32).
__device__ __forceinline__ float warp_min_nonneg(float v) {
    unsigned r;
    asm("redux.sync.min.u32 %0, %1, 0xffffffff;" : "=r"(r) : "r"(__float_as_uint(v)));
    return __uint_as_float(r);
}

__global__ __launch_bounds__(TPB, 1) void chamfer_fused(
    const float* __restrict__ x, const float* __restrict__ y, float* __restrict__ out)
{
    __shared__ __align__(16) float sy[YB * 8 + 16];    // 8KB + pad (prefetch overrun)
    __shared__ float srow[NWARP * YB];                 // 16KB: [w][y]
    __shared__ float red[NWARP];
    __shared__ int   s_last;

    const int tid  = threadIdx.x;
    const int lane = tid & 31;
    const int w    = tid >> 5;
    const int xh   = blockIdx.x;          // 0..1
    const int yb   = blockIdx.y;          // 0..NYB-1
    const int b    = blockIdx.z;          // 0..BS-1

    // Stage y-tile: per y 32B {yx,yx, yy,yy, yz,yz, ysq,ysq}.
    if (tid < YB) {
        const float* yp = y + ((size_t)b * NPTS + (size_t)yb * YB + tid) * 3;
        float a = yp[0], c = yp[1], d = yp[2];
        float qs = fmaf(a, a, fmaf(c, c, d * d));
        float4* o = (float4*)(sy + tid * 8);
        o[0] = make_float4(a, a, c, c);
        o[1] = make_float4(d, d, qs, qs);
    }
    if (tid >= TPB - 16) sy[YB * 8 + (tid - (TPB - 16))] = 0.0f;   // pad

    // Lane's 4 x-points -> packed registers (xsq as chain seed).
    ull Xp[SLOTS], Yq[SLOTS], Zp[SLOTS], Hp[SLOTS];
    {
        const float* xb = x + ((size_t)b * NPTS + (size_t)xh * XH + (size_t)w * XPW) * 3;
        #pragma unroll
        for (int j = 0; j < SLOTS; ++j) {
            int i0 = (2 * j) * 32 + lane;
            int i1 = i0 + 32;
            float x0 = xb[3 * i0 + 0], y0 = xb[3 * i0 + 1], z0 = xb[3 * i0 + 2];
            float x1 = xb[3 * i1 + 0], y1 = xb[3 * i1 + 1], z1 = xb[3 * i1 + 2];
            Xp[j] = pack2(-2.0f * x0, -2.0f * x1);
            Yq[j] = pack2(-2.0f * y0, -2.0f * y1);
            Zp[j] = pack2(-2.0f * z0, -2.0f * z1);
            Hp[j] = pack2(fmaf(x0, x0, fmaf(y0, y0, z0 * z0)),
                          fmaf(x1, x1, fmaf(y1, y1, z1 * z1)));
        }
    }

    float colacc[2 * SLOTS];
    #pragma unroll
    for (int k = 0; k < 2 * SLOTS; ++k) colacc[k] = 3.402823466e+38f;

    __syncthreads();

    unsigned sya = (unsigned)__cvta_generic_to_shared(sy);

    #define YLOAD(A_, B_, off)                                                     \
        asm("ld.shared.v2.u64 {%0,%1}, [%2+" #off "];" : "=l"(A_), "=l"(B_) : "r"(sya))

    ull Ya0, Yb0, Yc0, Ys0, Ya1, Yb1, Yc1, Ys1;
    YLOAD(Ya0, Yb0, 0); YLOAD(Yc0, Ys0, 16);

    #define YBODY(YA, YBv, YC, YS, yy)                                             \
        {                                                                          \
            float rm = 3.402823466e+38f;                                           \
            _Pragma("unroll")                                                      \
            for (int j = 0; j < SLOTS; ++j) {                                      \
                ull t = fma2(Xp[j], (YA), Hp[j]);                                  \
                t = fma2(Yq[j], (YBv), t);                                         \
                t = fma2(Zp[j], (YC), t);                                          \
                ull u = add2(t, (YS));         /* full dist^2, >= 0 */             \
                float c0, c1;                                                      \
                unpack2(u, c0, c1);                                                \
                colacc[2 * j]     = fminf(colacc[2 * j], c0);                      \
                colacc[2 * j + 1] = fminf(colacc[2 * j + 1], c1);                  \
                rm = fminf(rm, fminf(c0, c1));                                     \
            }                                                                      \
            rm = warp_min_nonneg(rm);                                              \
            if (lane == 0) srow[w * YB + (yy)] = rm;                               \
        }

    #pragma unroll 1
    for (int yy = 0; yy < YB; yy += 2) {
        sya += 64;
        YLOAD(Ya1, Yb1, -32); YLOAD(Yc1, Ys1, -16);    // prefetch yy+1
        YBODY(Ya0, Yb0, Yc0, Ys0, yy);
        YLOAD(Ya0, Yb0, 0);   YLOAD(Yc0, Ys0, 16);     // prefetch yy+2 (pad last)
        YBODY(Ya1, Yb1, Yc1, Ys1, yy + 1);
    }
    #undef YBODY
    #undef YLOAD

    __syncthreads();

    // Row combine (min over 16 warps) -> global [b][y][xh] (full dist^2).
    if (tid < YB) {
        float m = srow[tid];
        #pragma unroll
        for (int ww = 1; ww < NWARP; ++ww) m = fminf(m, srow[ww * YB + tid]);
        g_rowpart[((size_t)b * NPTS + (yb * YB + tid)) * 2 + xh] = m;
    }

    // Col partials -> global (coalesced).
    {
        float* cp = &g_colpart[((size_t)b * NYB + yb) * NPTS + (size_t)xh * XH + (size_t)w * XPW];
        #pragma unroll
        for (int kk = 0; kk < 2 * SLOTS; ++kk)
            cp[kk * 32 + lane] = colacc[kk];
    }

    // ---- Per-batch finisher (last of 32 blocks for batch b). ----
    __threadfence();
    if (tid == 0)
        s_last = (atomicAdd(&g_bc[b], 1u) == BPB - 1) ? 1 : 0;
    __syncthreads();

    if (s_last) {
        if (tid == 0) g_bc[b] = 0;         // self-reset for graph replay
        float acc = 0.0f;
        // Cols: per x, min over 16 yb partials.
        #pragma unroll 2
        for (int xi = tid; xi < NPTS; xi += TPB) {
            float m = 3.402823466e+38f;
            #pragma unroll
            for (int u = 0; u < NYB; ++u)
                m = fminf(m, __ldcg(&g_colpart[((size_t)b * NYB + u) * NPTS + xi]));
            acc += sqrtf(1e-6f + m);
        }
        // Rows: per y, min over 2 xh partials.
        #pragma unroll 2
        for (int yi = tid; yi < NPTS; yi += TPB) {
            const float* rp = &g_rowpart[((size_t)b * NPTS + yi) * 2];
            float m = fminf(__ldcg(rp), __ldcg(rp + 1));
            acc += sqrtf(1e-6f + m);
        }
        #pragma unroll
        for (int off = 16; off; off >>= 1)
            acc += __shfl_down_sync(0xFFFFFFFFu, acc, off);
        if (lane == 0) red[w] = acc;
        __syncthreads();
        if (tid == 0) {
            float t = 0.0f;
            #pragma unroll
            for (int i = 0; i < NWARP; ++i) t += red[i];
            g_bsum[b] = t;
            __threadfence();
            if (atomicAdd(&g_fc, 1u) == BS - 1) {
                volatile float* gs = g_bsum;
                float tot = gs[0] + gs[1] + gs[2] + gs[3];
                out[0] = tot * (1.0f / 16384.0f);   // (S1 + S2) / (BS * NPTS)
                g_fc = 0;                            // self-reset
            }
        }
    }
}

extern "C" void kernel_launch(void* const* d_in, const int* in_sizes, int n_in,
                              void* d_out, int out_size)
{
    const float* x = (const float*)d_in[0];
    const float* y = (const float*)d_in[1];
    float* out = (float*)d_out;

    chamfer_fused<<<dim3(2, NYB, BS), TPB>>>(x, y, out);
}